// round 15
// baseline (speedup 1.0000x reference)
#include <cuda_runtime.h>

// ---------------------------------------------------------------------------
// HierarchicalHeteroGraphSage — GB300 sm_103a
//
// Pipeline:
//   0) zero scratch (agg buffers + counts)
//   1) L0 edge scatter (fp32 atomics, dst-limit pruned), 3 relations x (h1,h2)
//   2) normalize (sum -> mean)
//   3) fused multi-segment SGEMM (fma.rn.f32x2) + bias + relu -> hp, ha
//   4) L1 edge scatter (256-dim)
//   5) normalize
//   6) fused SGEMM -> xp1 (relu)
//   7) SGEMM xp1 @ lin_W + lin_b -> out
// ---------------------------------------------------------------------------

namespace hhgs {

constexpr long long NP_ALL = 304096;
constexpr long long NP_H01 = 104096;
constexpr long long NA_ALL = 154096;
constexpr long long NA_H01 = 54096;

// padded to multiples of 128 rows so GEMM A-tiles never need row guards
constexpr long long NPP = 104192;   // 128 * 814
constexpr long long NAP = 54144;    // 128 * 423

// ---- scratch layout (float offsets). Regions needing per-call zeroing first.
constexpr long long OFF_AGG_C  = 0;                          // [NPP x 128]
constexpr long long OFF_AGG_W  = OFF_AGG_C  + NPP * 128;     // [NPP x 128]
constexpr long long OFF_AGG_R  = OFF_AGG_W  + NPP * 128;     // [NAP x 128]
constexpr long long OFF_AGG_C1 = OFF_AGG_R  + NAP * 128;     // [NPP x 256]
constexpr long long OFF_AGG_W1 = OFF_AGG_C1 + NPP * 256;     // [NPP x 256]
constexpr long long OFF_CNT_C  = OFF_AGG_W1 + NPP * 256;     // [NPP]
constexpr long long OFF_CNT_W  = OFF_CNT_C  + NPP;           // [NPP]
constexpr long long OFF_CNT_R  = OFF_CNT_W  + NPP;           // [NAP]
constexpr long long OFF_CNT_C1 = OFF_CNT_R  + NAP;           // [NPP]
constexpr long long OFF_CNT_W1 = OFF_CNT_C1 + NPP;           // [NPP]
constexpr long long ZERO_END   = OFF_CNT_W1 + NPP;
// not zeroed per call (fully overwritten in valid rows; padded rows stay 0 from
// module-load zero-init and are never stored to):
constexpr long long OFF_HP     = ZERO_END;                   // [NPP x 256]
constexpr long long OFF_HA     = OFF_HP  + NPP * 256;        // [NAP x 256]
constexpr long long OFF_XP1    = OFF_HA  + NAP * 256;        // [NPP x 256]
constexpr long long OFF_WRP    = OFF_XP1 + NPP * 256;        // [128 x 256]
constexpr long long OFF_BP     = OFF_WRP + 128 * 256;        // [256]
constexpr long long OFF_WR1    = OFF_BP  + 256;              // [256 x 256]
constexpr long long OFF_B1     = OFF_WR1 + 256 * 256;        // [256]
constexpr long long TOTAL      = OFF_B1  + 256;

} // namespace hhgs

__device__ float g_scratch[hhgs::TOTAL];

// ---------------------------------------------------------------------------
// tiny utility kernels
// ---------------------------------------------------------------------------

__global__ void k_zero(long long n4) {
    long long i = (long long)blockIdx.x * 256 + threadIdx.x;
    if (i < n4) ((float4*)g_scratch)[i] = make_float4(0.f, 0.f, 0.f, 0.f);
}

__global__ void k_add(const float* __restrict__ a, const float* __restrict__ b,
                      float* __restrict__ o, int n) {
    int i = blockIdx.x * 256 + threadIdx.x;
    if (i < n) o[i] = a[i] + b[i];
}

// scale each row of agg by 1/max(cnt[row],1).  n4 = M * (K/4), row = i >> shift
__global__ void k_norm(float* __restrict__ agg, const float* __restrict__ cnt,
                       long long n4, int shift) {
    long long i = (long long)blockIdx.x * 256 + threadIdx.x;
    if (i >= n4) return;
    long long row = i >> shift;
    float s = 1.0f / fmaxf(__ldg(cnt + row), 1.0f);
    float4 v = ((float4*)agg)[i];
    v.x *= s; v.y *= s; v.z *= s; v.w *= s;
    ((float4*)agg)[i] = v;
}

// ---------------------------------------------------------------------------
// edge scatter: one warp per edge (128-dim), 4 floats per lane
// ---------------------------------------------------------------------------

__global__ void k_scatter128(const float* __restrict__ feat,
                             const int* __restrict__ srcIdx,
                             const int* __restrict__ dstIdx,
                             int E, int dstLimit,
                             float* __restrict__ agg, float* __restrict__ cnt) {
    long long idx = (long long)blockIdx.x * 256 + threadIdx.x;
    if (idx >= (long long)E * 32) return;
    int e = (int)(idx >> 5);
    int c = (int)(idx & 31);
    int d = __ldg(dstIdx + e);
    if (d >= dstLimit) return;                       // warp-uniform
    int s = __ldg(srcIdx + e);
    float4 v = __ldg((const float4*)feat + (long long)s * 32 + c);
    float* o = agg + (long long)d * 128 + c * 4;
    atomicAdd(o + 0, v.x);
    atomicAdd(o + 1, v.y);
    atomicAdd(o + 2, v.z);
    atomicAdd(o + 3, v.w);
    if (c == 0) atomicAdd(cnt + d, 1.0f);
}

// 256-dim variant: two warps per edge
__global__ void k_scatter256(const float* __restrict__ feat,
                             const int* __restrict__ srcIdx,
                             const int* __restrict__ dstIdx,
                             int E, int dstLimit,
                             float* __restrict__ agg, float* __restrict__ cnt) {
    long long idx = (long long)blockIdx.x * 256 + threadIdx.x;
    if (idx >= (long long)E * 64) return;
    int e = (int)(idx >> 6);
    int c = (int)(idx & 63);
    int d = __ldg(dstIdx + e);
    if (d >= dstLimit) return;                       // warp-uniform
    int s = __ldg(srcIdx + e);
    float4 v = __ldg((const float4*)feat + (long long)s * 64 + c);
    float* o = agg + (long long)d * 256 + c * 4;
    atomicAdd(o + 0, v.x);
    atomicAdd(o + 1, v.y);
    atomicAdd(o + 2, v.z);
    atomicAdd(o + 3, v.w);
    if (c == 0) atomicAdd(cnt + d, 1.0f);
}

// ---------------------------------------------------------------------------
// multi-segment SGEMM with packed f32x2 FMA (Blackwell FFMA2)
//   C[M,N] = sum_s A_s[M,K_s] @ B_s[K_s,N]  + bias (row-broadcast), opt. relu
//   BM=128, BN=128, BK=16, 256 threads, 8x8 micro-tile per thread.
//   A rows beyond M may be read (scratch is padded / inputs oversized);
//   stores are guarded by row<M and col<N.  K_s must be a multiple of 16.
// ---------------------------------------------------------------------------

__device__ __forceinline__ unsigned long long f32x2_dup(float a) {
    unsigned long long r;
    asm("mov.b64 %0, {%1, %1};" : "=l"(r) : "f"(a));
    return r;
}
__device__ __forceinline__ unsigned long long f32x2_pack(float a, float b) {
    unsigned long long r;
    asm("mov.b64 %0, {%1, %2};" : "=l"(r) : "f"(a), "f"(b));
    return r;
}

__global__ __launch_bounds__(256, 2)
void k_gemm_ms(const float* __restrict__ A0, const float* __restrict__ B0, int K0,
               const float* __restrict__ A1, const float* __restrict__ B1, int K1,
               const float* __restrict__ A2, const float* __restrict__ B2, int K2,
               const float* __restrict__ bias,
               float* __restrict__ C, int M, int N, int relu) {
    __shared__ __align__(16) float As[16][132];
    __shared__ __align__(16) float Bs[16][132];

    const int tid = threadIdx.x;
    const int tx = tid & 15;        // column group (8 cols)
    const int ty = tid >> 4;        // row group (8 rows)
    const int rowBase = blockIdx.x * 128;
    const int colBase = blockIdx.y * 128;

    unsigned long long acc[8][4];
    {
        const int c0 = colBase + tx * 8;
#pragma unroll
        for (int j = 0; j < 4; j++) {
            float b0 = (c0 + 2 * j     < N) ? __ldg(bias + c0 + 2 * j)     : 0.f;
            float b1 = (c0 + 2 * j + 1 < N) ? __ldg(bias + c0 + 2 * j + 1) : 0.f;
            unsigned long long p = f32x2_pack(b0, b1);
#pragma unroll
            for (int m = 0; m < 8; m++) acc[m][j] = p;
        }
    }

    const float* Aseg[3] = {A0, A1, A2};
    const float* Bseg[3] = {B0, B1, B2};
    const int    Kseg[3] = {K0, K1, K2};

    for (int s = 0; s < 3; s++) {
        const int K = Kseg[s];
        if (K == 0) continue;
        const float* __restrict__ A = Aseg[s];
        const float* __restrict__ B = Bseg[s];

        for (int k0 = 0; k0 < K; k0 += 16) {
            float4 aval[2], bval[2];
#pragma unroll
            for (int i = 0; i < 2; i++) {
                int id = tid + i * 256;                 // 0..511
                // A tile: 128 rows x 16 cols (4 float4 per row)
                int r  = id >> 2;
                int kk = (id & 3) * 4;
                aval[i] = *(const float4*)(A + (long long)(rowBase + r) * K + k0 + kk);
                // B tile: 16 rows x 128 cols (32 float4 per row)
                int kb = id >> 5;
                int nn = (id & 31) * 4;
                int nc = colBase + nn;
                if (nc + 3 < N)
                    bval[i] = *(const float4*)(B + (long long)(k0 + kb) * N + nc);
                else
                    bval[i] = make_float4(0.f, 0.f, 0.f, 0.f);
            }
            __syncthreads();   // previous compute done before overwriting smem
#pragma unroll
            for (int i = 0; i < 2; i++) {
                int id = tid + i * 256;
                int r  = id >> 2;
                int kk = (id & 3) * 4;
                As[kk + 0][r] = aval[i].x;
                As[kk + 1][r] = aval[i].y;
                As[kk + 2][r] = aval[i].z;
                As[kk + 3][r] = aval[i].w;
                int kb = id >> 5;
                int nn = (id & 31) * 4;
                *(float4*)&Bs[kb][nn] = bval[i];
            }
            __syncthreads();

#pragma unroll
            for (int kk = 0; kk < 16; kk++) {
                float4 a0 = *(const float4*)&As[kk][ty * 8];
                float4 a1 = *(const float4*)&As[kk][ty * 8 + 4];
                ulonglong2 bq0 = *(const ulonglong2*)&Bs[kk][tx * 8];
                ulonglong2 bq1 = *(const ulonglong2*)&Bs[kk][tx * 8 + 4];
                unsigned long long b[4] = {bq0.x, bq0.y, bq1.x, bq1.y};
                float av[8] = {a0.x, a0.y, a0.z, a0.w, a1.x, a1.y, a1.z, a1.w};
#pragma unroll
                for (int m = 0; m < 8; m++) {
                    unsigned long long am = f32x2_dup(av[m]);
#pragma unroll
                    for (int j = 0; j < 4; j++)
                        asm("fma.rn.f32x2 %0, %1, %2, %0;"
                            : "+l"(acc[m][j]) : "l"(am), "l"(b[j]));
                }
            }
        }
    }

    // epilogue
#pragma unroll
    for (int m = 0; m < 8; m++) {
        int r = rowBase + ty * 8 + m;
        if (r >= M) continue;
#pragma unroll
        for (int j = 0; j < 4; j++) {
            int cix = colBase + tx * 8 + 2 * j;
            if (cix >= N) continue;          // N is even -> cix+1 < N too
            float f0, f1;
            asm("mov.b64 {%0, %1}, %2;" : "=f"(f0), "=f"(f1) : "l"(acc[m][j]));
            if (relu) { f0 = fmaxf(f0, 0.f); f1 = fmaxf(f1, 0.f); }
            *(float2*)(C + (long long)r * N + cix) = make_float2(f0, f1);
        }
    }
}

// ---------------------------------------------------------------------------
// host orchestration
// ---------------------------------------------------------------------------

static inline int nb(long long n, int t) { return (int)((n + t - 1) / t); }

extern "C" void kernel_launch(void* const* d_in, const int* in_sizes, int n_in,
                              void* d_out, int out_size) {
    using namespace hhgs;

    const float* x_paper  = (const float*)d_in[0];
    const float* x_author = (const float*)d_in[1];
    const float* l0c_Wl = (const float*)d_in[2];
    const float* l0c_b  = (const float*)d_in[3];
    const float* l0c_Wr = (const float*)d_in[4];
    const float* l0w_Wl = (const float*)d_in[5];
    const float* l0w_b  = (const float*)d_in[6];
    const float* l0w_Wr = (const float*)d_in[7];
    const float* l0r_Wl = (const float*)d_in[8];
    const float* l0r_b  = (const float*)d_in[9];
    const float* l0r_Wr = (const float*)d_in[10];
    const float* l1c_Wl = (const float*)d_in[11];
    const float* l1c_b  = (const float*)d_in[12];
    const float* l1c_Wr = (const float*)d_in[13];
    const float* l1w_Wl = (const float*)d_in[14];
    const float* l1w_b  = (const float*)d_in[15];
    const float* l1w_Wr = (const float*)d_in[16];
    // d_in[17..19] = l1_rev_* : unused by the reference's output path
    const float* lin_W  = (const float*)d_in[20];
    const float* lin_b  = (const float*)d_in[21];
    const int* ec1 = (const int*)d_in[22];
    const int* ec2 = (const int*)d_in[23];
    const int* ew1 = (const int*)d_in[24];
    const int* ew2 = (const int*)d_in[25];
    const int* er1 = (const int*)d_in[26];
    const int* er2 = (const int*)d_in[27];
    const int Ec1 = in_sizes[22] / 2, Ec2 = in_sizes[23] / 2;
    const int Ew1 = in_sizes[24] / 2, Ew2 = in_sizes[25] / 2;
    const int Er1 = in_sizes[26] / 2, Er2 = in_sizes[27] / 2;

    float* S = nullptr;
    cudaGetSymbolAddress((void**)&S, g_scratch);
    float* agg_c  = S + OFF_AGG_C;
    float* agg_w  = S + OFF_AGG_W;
    float* agg_r  = S + OFF_AGG_R;
    float* agg_c1 = S + OFF_AGG_C1;
    float* agg_w1 = S + OFF_AGG_W1;
    float* cnt_c  = S + OFF_CNT_C;
    float* cnt_w  = S + OFF_CNT_W;
    float* cnt_r  = S + OFF_CNT_R;
    float* cnt_c1 = S + OFF_CNT_C1;
    float* cnt_w1 = S + OFF_CNT_W1;
    float* hp     = S + OFF_HP;
    float* ha     = S + OFF_HA;
    float* xp1    = S + OFF_XP1;
    float* WrP    = S + OFF_WRP;
    float* bP     = S + OFF_BP;
    float* Wr1    = S + OFF_WR1;
    float* b1     = S + OFF_B1;

    // 0) zero accumulation buffers + counts
    {
        long long n4 = ZERO_END / 4;
        k_zero<<<nb(n4, 256), 256>>>(n4);
    }

    // precombine Wr / b for fused dst-type GEMMs (tiny)
    k_add<<<nb(128 * 256, 256), 256>>>(l0c_Wr, l0w_Wr, WrP, 128 * 256);
    k_add<<<1, 256>>>(l0c_b, l0w_b, bP, 256);
    k_add<<<nb(256 * 256, 256), 256>>>(l1c_Wr, l1w_Wr, Wr1, 256 * 256);
    k_add<<<1, 256>>>(l1c_b, l1w_b, b1, 256);

    // 1) layer-0 scatter (dst-limit pruned to rows actually consumed later)
    k_scatter128<<<nb((long long)Ec1 * 32, 256), 256>>>(x_paper,  ec1, ec1 + Ec1, Ec1, (int)NP_H01, agg_c, cnt_c);
    k_scatter128<<<nb((long long)Ec2 * 32, 256), 256>>>(x_paper,  ec2, ec2 + Ec2, Ec2, (int)NP_H01, agg_c, cnt_c);
    k_scatter128<<<nb((long long)Ew1 * 32, 256), 256>>>(x_author, ew1, ew1 + Ew1, Ew1, (int)NP_H01, agg_w, cnt_w);
    k_scatter128<<<nb((long long)Ew2 * 32, 256), 256>>>(x_author, ew2, ew2 + Ew2, Ew2, (int)NP_H01, agg_w, cnt_w);
    k_scatter128<<<nb((long long)Er1 * 32, 256), 256>>>(x_paper,  er1, er1 + Er1, Er1, (int)NA_H01, agg_r, cnt_r);
    k_scatter128<<<nb((long long)Er2 * 32, 256), 256>>>(x_paper,  er2, er2 + Er2, Er2, (int)NA_H01, agg_r, cnt_r);

    // 2) sum -> mean   (K=128 -> 32 float4/row -> shift 5)
    k_norm<<<nb(NP_H01 * 32, 256), 256>>>(agg_c, cnt_c, NP_H01 * 32, 5);
    k_norm<<<nb(NP_H01 * 32, 256), 256>>>(agg_w, cnt_w, NP_H01 * 32, 5);
    k_norm<<<nb(NA_H01 * 32, 256), 256>>>(agg_r, cnt_r, NA_H01 * 32, 5);

    // 3) layer-0 GEMMs (+bias, relu)
    {
        dim3 g((unsigned)((NP_H01 + 127) / 128), 2);
        k_gemm_ms<<<g, 256>>>(agg_c, l0c_Wl, 128,
                              agg_w, l0w_Wl, 128,
                              x_paper, WrP, 128,
                              bP, hp, (int)NP_H01, 256, 1);
    }
    {
        dim3 g((unsigned)((NA_H01 + 127) / 128), 2);
        k_gemm_ms<<<g, 256>>>(agg_r, l0r_Wl, 128,
                              x_author, l0r_Wr, 128,
                              nullptr, nullptr, 0,
                              l0r_b, ha, (int)NA_H01, 256, 1);
    }

    // 4) layer-1 scatter (256-dim features)
    k_scatter256<<<nb((long long)Ec1 * 64, 256), 256>>>(hp, ec1, ec1 + Ec1, Ec1, (int)NP_H01, agg_c1, cnt_c1);
    k_scatter256<<<nb((long long)Ew1 * 64, 256), 256>>>(ha, ew1, ew1 + Ew1, Ew1, (int)NP_H01, agg_w1, cnt_w1);

    // 5) normalize (K=256 -> 64 float4/row -> shift 6)
    k_norm<<<nb(NP_H01 * 64, 256), 256>>>(agg_c1, cnt_c1, NP_H01 * 64, 6);
    k_norm<<<nb(NP_H01 * 64, 256), 256>>>(agg_w1, cnt_w1, NP_H01 * 64, 6);

    // 6) layer-1 GEMM (+bias, relu) -> xp1
    {
        dim3 g((unsigned)((NP_H01 + 127) / 128), 2);
        k_gemm_ms<<<g, 256>>>(agg_c1, l1c_Wl, 256,
                              agg_w1, l1w_Wl, 256,
                              hp, Wr1, 256,
                              b1, xp1, (int)NP_H01, 256, 1);
    }

    // 7) final linear: out = xp1 @ lin_W + lin_b   (N=64, single N-tile)
    {
        dim3 g((unsigned)((NP_H01 + 127) / 128), 1);
        k_gemm_ms<<<g, 256>>>(xp1, lin_W, 256,
                              nullptr, nullptr, 0,
                              nullptr, nullptr, 0,
                              lin_b, (float*)d_out, (int)NP_H01, 64, 0);
    }
}

// round 16
// speedup vs baseline: 1.0012x; 1.0012x over previous
#include <cuda_runtime.h>

// ---------------------------------------------------------------------------
// HierarchicalHeteroGraphSage — GB300 sm_103a
//
// Pipeline:
//   0) zero scratch (agg buffers + counts)
//   1) L0 edge scatter (fp32 atomics, dst-limit pruned), 3 relations x (h1,h2)
//   2) normalize (sum -> mean)
//   3) fused multi-segment SGEMM (fma.rn.f32x2) + bias + relu -> hp, ha
//   4) L1 edge scatter (256-dim)
//   5) normalize
//   6) fused SGEMM -> xp1 (relu)
//   7) SGEMM xp1 @ lin_W + lin_b -> out
// ---------------------------------------------------------------------------

namespace hhgs {

constexpr long long NP_ALL = 304096;
constexpr long long NP_H01 = 104096;
constexpr long long NA_ALL = 154096;
constexpr long long NA_H01 = 54096;

// padded to multiples of 128 rows so GEMM A-tiles never need row guards
constexpr long long NPP = 104192;   // 128 * 814
constexpr long long NAP = 54144;    // 128 * 423

// ---- scratch layout (float offsets). Regions needing per-call zeroing first.
constexpr long long OFF_AGG_C  = 0;                          // [NPP x 128]
constexpr long long OFF_AGG_W  = OFF_AGG_C  + NPP * 128;     // [NPP x 128]
constexpr long long OFF_AGG_R  = OFF_AGG_W  + NPP * 128;     // [NAP x 128]
constexpr long long OFF_AGG_C1 = OFF_AGG_R  + NAP * 128;     // [NPP x 256]
constexpr long long OFF_AGG_W1 = OFF_AGG_C1 + NPP * 256;     // [NPP x 256]
constexpr long long OFF_CNT_C  = OFF_AGG_W1 + NPP * 256;     // [NPP]
constexpr long long OFF_CNT_W  = OFF_CNT_C  + NPP;           // [NPP]
constexpr long long OFF_CNT_R  = OFF_CNT_W  + NPP;           // [NAP]
constexpr long long OFF_CNT_C1 = OFF_CNT_R  + NAP;           // [NPP]
constexpr long long OFF_CNT_W1 = OFF_CNT_C1 + NPP;           // [NPP]
constexpr long long ZERO_END   = OFF_CNT_W1 + NPP;
// not zeroed per call (fully overwritten in valid rows; padded rows stay 0 from
// module-load zero-init and are never stored to):
constexpr long long OFF_HP     = ZERO_END;                   // [NPP x 256]
constexpr long long OFF_HA     = OFF_HP  + NPP * 256;        // [NAP x 256]
constexpr long long OFF_XP1    = OFF_HA  + NAP * 256;        // [NPP x 256]
constexpr long long OFF_WRP    = OFF_XP1 + NPP * 256;        // [128 x 256]
constexpr long long OFF_BP     = OFF_WRP + 128 * 256;        // [256]
constexpr long long OFF_WR1    = OFF_BP  + 256;              // [256 x 256]
constexpr long long OFF_B1     = OFF_WR1 + 256 * 256;        // [256]
constexpr long long TOTAL      = OFF_B1  + 256;

} // namespace hhgs

__device__ float g_scratch[hhgs::TOTAL];

// ---------------------------------------------------------------------------
// tiny utility kernels
// ---------------------------------------------------------------------------

__global__ void k_zero(long long n4) {
    long long i = (long long)blockIdx.x * 256 + threadIdx.x;
    if (i < n4) ((float4*)g_scratch)[i] = make_float4(0.f, 0.f, 0.f, 0.f);
}

__global__ void k_add(const float* __restrict__ a, const float* __restrict__ b,
                      float* __restrict__ o, int n) {
    int i = blockIdx.x * 256 + threadIdx.x;
    if (i < n) o[i] = a[i] + b[i];
}

// scale each row of agg by 1/max(cnt[row],1).  n4 = M * (K/4), row = i >> shift
__global__ void k_norm(float* __restrict__ agg, const float* __restrict__ cnt,
                       long long n4, int shift) {
    long long i = (long long)blockIdx.x * 256 + threadIdx.x;
    if (i >= n4) return;
    long long row = i >> shift;
    float s = 1.0f / fmaxf(__ldg(cnt + row), 1.0f);
    float4 v = ((float4*)agg)[i];
    v.x *= s; v.y *= s; v.z *= s; v.w *= s;
    ((float4*)agg)[i] = v;
}

// ---------------------------------------------------------------------------
// edge scatter: one warp per edge (128-dim), 4 floats per lane
// ---------------------------------------------------------------------------

__global__ void k_scatter128(const float* __restrict__ feat,
                             const int* __restrict__ srcIdx,
                             const int* __restrict__ dstIdx,
                             int E, int dstLimit,
                             float* __restrict__ agg, float* __restrict__ cnt) {
    long long idx = (long long)blockIdx.x * 256 + threadIdx.x;
    if (idx >= (long long)E * 32) return;
    int e = (int)(idx >> 5);
    int c = (int)(idx & 31);
    int d = __ldg(dstIdx + e);
    if (d >= dstLimit) return;                       // warp-uniform
    int s = __ldg(srcIdx + e);
    float4 v = __ldg((const float4*)feat + (long long)s * 32 + c);
    float* o = agg + (long long)d * 128 + c * 4;
    atomicAdd(o + 0, v.x);
    atomicAdd(o + 1, v.y);
    atomicAdd(o + 2, v.z);
    atomicAdd(o + 3, v.w);
    if (c == 0) atomicAdd(cnt + d, 1.0f);
}

// 256-dim variant: two warps per edge
__global__ void k_scatter256(const float* __restrict__ feat,
                             const int* __restrict__ srcIdx,
                             const int* __restrict__ dstIdx,
                             int E, int dstLimit,
                             float* __restrict__ agg, float* __restrict__ cnt) {
    long long idx = (long long)blockIdx.x * 256 + threadIdx.x;
    if (idx >= (long long)E * 64) return;
    int e = (int)(idx >> 6);
    int c = (int)(idx & 63);
    int d = __ldg(dstIdx + e);
    if (d >= dstLimit) return;                       // warp-uniform
    int s = __ldg(srcIdx + e);
    float4 v = __ldg((const float4*)feat + (long long)s * 64 + c);
    float* o = agg + (long long)d * 256 + c * 4;
    atomicAdd(o + 0, v.x);
    atomicAdd(o + 1, v.y);
    atomicAdd(o + 2, v.z);
    atomicAdd(o + 3, v.w);
    if (c == 0) atomicAdd(cnt + d, 1.0f);
}

// ---------------------------------------------------------------------------
// multi-segment SGEMM with packed f32x2 FMA (Blackwell FFMA2)
//   C[M,N] = sum_s A_s[M,K_s] @ B_s[K_s,N]  + bias (row-broadcast), opt. relu
//   BM=128, BN=128, BK=16, 256 threads, 8x8 micro-tile per thread.
//   A rows beyond M may be read (scratch is padded / inputs oversized);
//   stores are guarded by row<M and col<N.  K_s must be a multiple of 16.
// ---------------------------------------------------------------------------

__device__ __forceinline__ unsigned long long f32x2_dup(float a) {
    unsigned long long r;
    asm("mov.b64 %0, {%1, %1};" : "=l"(r) : "f"(a));
    return r;
}
__device__ __forceinline__ unsigned long long f32x2_pack(float a, float b) {
    unsigned long long r;
    asm("mov.b64 %0, {%1, %2};" : "=l"(r) : "f"(a), "f"(b));
    return r;
}

__global__ __launch_bounds__(256, 2)
void k_gemm_ms(const float* __restrict__ A0, const float* __restrict__ B0, int K0,
               const float* __restrict__ A1, const float* __restrict__ B1, int K1,
               const float* __restrict__ A2, const float* __restrict__ B2, int K2,
               const float* __restrict__ bias,
               float* __restrict__ C, int M, int N, int relu) {
    __shared__ __align__(16) float As[16][132];
    __shared__ __align__(16) float Bs[16][132];

    const int tid = threadIdx.x;
    const int tx = tid & 15;        // column group (8 cols)
    const int ty = tid >> 4;        // row group (8 rows)
    const int rowBase = blockIdx.x * 128;
    const int colBase = blockIdx.y * 128;

    unsigned long long acc[8][4];
    {
        const int c0 = colBase + tx * 8;
#pragma unroll
        for (int j = 0; j < 4; j++) {
            float b0 = (c0 + 2 * j     < N) ? __ldg(bias + c0 + 2 * j)     : 0.f;
            float b1 = (c0 + 2 * j + 1 < N) ? __ldg(bias + c0 + 2 * j + 1) : 0.f;
            unsigned long long p = f32x2_pack(b0, b1);
#pragma unroll
            for (int m = 0; m < 8; m++) acc[m][j] = p;
        }
    }

    const float* Aseg[3] = {A0, A1, A2};
    const float* Bseg[3] = {B0, B1, B2};
    const int    Kseg[3] = {K0, K1, K2};

    for (int s = 0; s < 3; s++) {
        const int K = Kseg[s];
        if (K == 0) continue;
        const float* __restrict__ A = Aseg[s];
        const float* __restrict__ B = Bseg[s];

        for (int k0 = 0; k0 < K; k0 += 16) {
            float4 aval[2], bval[2];
#pragma unroll
            for (int i = 0; i < 2; i++) {
                int id = tid + i * 256;                 // 0..511
                // A tile: 128 rows x 16 cols (4 float4 per row)
                int r  = id >> 2;
                int kk = (id & 3) * 4;
                aval[i] = *(const float4*)(A + (long long)(rowBase + r) * K + k0 + kk);
                // B tile: 16 rows x 128 cols (32 float4 per row)
                int kb = id >> 5;
                int nn = (id & 31) * 4;
                int nc = colBase + nn;
                if (nc + 3 < N)
                    bval[i] = *(const float4*)(B + (long long)(k0 + kb) * N + nc);
                else
                    bval[i] = make_float4(0.f, 0.f, 0.f, 0.f);
            }
            __syncthreads();   // previous compute done before overwriting smem
#pragma unroll
            for (int i = 0; i < 2; i++) {
                int id = tid + i * 256;
                int r  = id >> 2;
                int kk = (id & 3) * 4;
                As[kk + 0][r] = aval[i].x;
                As[kk + 1][r] = aval[i].y;
                As[kk + 2][r] = aval[i].z;
                As[kk + 3][r] = aval[i].w;
                int kb = id >> 5;
                int nn = (id & 31) * 4;
                *(float4*)&Bs[kb][nn] = bval[i];
            }
            __syncthreads();

#pragma unroll
            for (int kk = 0; kk < 16; kk++) {
                float4 a0 = *(const float4*)&As[kk][ty * 8];
                float4 a1 = *(const float4*)&As[kk][ty * 8 + 4];
                ulonglong2 bq0 = *(const ulonglong2*)&Bs[kk][tx * 8];
                ulonglong2 bq1 = *(const ulonglong2*)&Bs[kk][tx * 8 + 4];
                unsigned long long b[4] = {bq0.x, bq0.y, bq1.x, bq1.y};
                float av[8] = {a0.x, a0.y, a0.z, a0.w, a1.x, a1.y, a1.z, a1.w};
#pragma unroll
                for (int m = 0; m < 8; m++) {
                    unsigned long long am = f32x2_dup(av[m]);
#pragma unroll
                    for (int j = 0; j < 4; j++)
                        asm("fma.rn.f32x2 %0, %1, %2, %0;"
                            : "+l"(acc[m][j]) : "l"(am), "l"(b[j]));
                }
            }
        }
    }

    // epilogue
#pragma unroll
    for (int m = 0; m < 8; m++) {
        int r = rowBase + ty * 8 + m;
        if (r >= M) continue;
#pragma unroll
        for (int j = 0; j < 4; j++) {
            int cix = colBase + tx * 8 + 2 * j;
            if (cix >= N) continue;          // N is even -> cix+1 < N too
            float f0, f1;
            asm("mov.b64 {%0, %1}, %2;" : "=f"(f0), "=f"(f1) : "l"(acc[m][j]));
            if (relu) { f0 = fmaxf(f0, 0.f); f1 = fmaxf(f1, 0.f); }
            *(float2*)(C + (long long)r * N + cix) = make_float2(f0, f1);
        }
    }
}

// ---------------------------------------------------------------------------
// host orchestration
// ---------------------------------------------------------------------------

static inline int nb(long long n, int t) { return (int)((n + t - 1) / t); }

extern "C" void kernel_launch(void* const* d_in, const int* in_sizes, int n_in,
                              void* d_out, int out_size) {
    using namespace hhgs;

    const float* x_paper  = (const float*)d_in[0];
    const float* x_author = (const float*)d_in[1];
    const float* l0c_Wl = (const float*)d_in[2];
    const float* l0c_b  = (const float*)d_in[3];
    const float* l0c_Wr = (const float*)d_in[4];
    const float* l0w_Wl = (const float*)d_in[5];
    const float* l0w_b  = (const float*)d_in[6];
    const float* l0w_Wr = (const float*)d_in[7];
    const float* l0r_Wl = (const float*)d_in[8];
    const float* l0r_b  = (const float*)d_in[9];
    const float* l0r_Wr = (const float*)d_in[10];
    const float* l1c_Wl = (const float*)d_in[11];
    const float* l1c_b  = (const float*)d_in[12];
    const float* l1c_Wr = (const float*)d_in[13];
    const float* l1w_Wl = (const float*)d_in[14];
    const float* l1w_b  = (const float*)d_in[15];
    const float* l1w_Wr = (const float*)d_in[16];
    // d_in[17..19] = l1_rev_* : unused by the reference's output path
    const float* lin_W  = (const float*)d_in[20];
    const float* lin_b  = (const float*)d_in[21];
    const int* ec1 = (const int*)d_in[22];
    const int* ec2 = (const int*)d_in[23];
    const int* ew1 = (const int*)d_in[24];
    const int* ew2 = (const int*)d_in[25];
    const int* er1 = (const int*)d_in[26];
    const int* er2 = (const int*)d_in[27];
    const int Ec1 = in_sizes[22] / 2, Ec2 = in_sizes[23] / 2;
    const int Ew1 = in_sizes[24] / 2, Ew2 = in_sizes[25] / 2;
    const int Er1 = in_sizes[26] / 2, Er2 = in_sizes[27] / 2;

    float* S = nullptr;
    cudaGetSymbolAddress((void**)&S, g_scratch);
    float* agg_c  = S + OFF_AGG_C;
    float* agg_w  = S + OFF_AGG_W;
    float* agg_r  = S + OFF_AGG_R;
    float* agg_c1 = S + OFF_AGG_C1;
    float* agg_w1 = S + OFF_AGG_W1;
    float* cnt_c  = S + OFF_CNT_C;
    float* cnt_w  = S + OFF_CNT_W;
    float* cnt_r  = S + OFF_CNT_R;
    float* cnt_c1 = S + OFF_CNT_C1;
    float* cnt_w1 = S + OFF_CNT_W1;
    float* hp     = S + OFF_HP;
    float* ha     = S + OFF_HA;
    float* xp1    = S + OFF_XP1;
    float* WrP    = S + OFF_WRP;
    float* bP     = S + OFF_BP;
    float* Wr1    = S + OFF_WR1;
    float* b1     = S + OFF_B1;

    // 0) zero accumulation buffers + counts
    {
        long long n4 = ZERO_END / 4;
        k_zero<<<nb(n4, 256), 256>>>(n4);
    }

    // precombine Wr / b for fused dst-type GEMMs (tiny)
    k_add<<<nb(128 * 256, 256), 256>>>(l0c_Wr, l0w_Wr, WrP, 128 * 256);
    k_add<<<1, 256>>>(l0c_b, l0w_b, bP, 256);
    k_add<<<nb(256 * 256, 256), 256>>>(l1c_Wr, l1w_Wr, Wr1, 256 * 256);
    k_add<<<1, 256>>>(l1c_b, l1w_b, b1, 256);

    // 1) layer-0 scatter (dst-limit pruned to rows actually consumed later)
    k_scatter128<<<nb((long long)Ec1 * 32, 256), 256>>>(x_paper,  ec1, ec1 + Ec1, Ec1, (int)NP_H01, agg_c, cnt_c);
    k_scatter128<<<nb((long long)Ec2 * 32, 256), 256>>>(x_paper,  ec2, ec2 + Ec2, Ec2, (int)NP_H01, agg_c, cnt_c);
    k_scatter128<<<nb((long long)Ew1 * 32, 256), 256>>>(x_author, ew1, ew1 + Ew1, Ew1, (int)NP_H01, agg_w, cnt_w);
    k_scatter128<<<nb((long long)Ew2 * 32, 256), 256>>>(x_author, ew2, ew2 + Ew2, Ew2, (int)NP_H01, agg_w, cnt_w);
    k_scatter128<<<nb((long long)Er1 * 32, 256), 256>>>(x_paper,  er1, er1 + Er1, Er1, (int)NA_H01, agg_r, cnt_r);
    k_scatter128<<<nb((long long)Er2 * 32, 256), 256>>>(x_paper,  er2, er2 + Er2, Er2, (int)NA_H01, agg_r, cnt_r);

    // 2) sum -> mean   (K=128 -> 32 float4/row -> shift 5)
    k_norm<<<nb(NP_H01 * 32, 256), 256>>>(agg_c, cnt_c, NP_H01 * 32, 5);
    k_norm<<<nb(NP_H01 * 32, 256), 256>>>(agg_w, cnt_w, NP_H01 * 32, 5);
    k_norm<<<nb(NA_H01 * 32, 256), 256>>>(agg_r, cnt_r, NA_H01 * 32, 5);

    // 3) layer-0 GEMMs (+bias, relu)
    {
        dim3 g((unsigned)((NP_H01 + 127) / 128), 2);
        k_gemm_ms<<<g, 256>>>(agg_c, l0c_Wl, 128,
                              agg_w, l0w_Wl, 128,
                              x_paper, WrP, 128,
                              bP, hp, (int)NP_H01, 256, 1);
    }
    {
        dim3 g((unsigned)((NA_H01 + 127) / 128), 2);
        k_gemm_ms<<<g, 256>>>(agg_r, l0r_Wl, 128,
                              x_author, l0r_Wr, 128,
                              nullptr, nullptr, 0,
                              l0r_b, ha, (int)NA_H01, 256, 1);
    }

    // 4) layer-1 scatter (256-dim features)
    k_scatter256<<<nb((long long)Ec1 * 64, 256), 256>>>(hp, ec1, ec1 + Ec1, Ec1, (int)NP_H01, agg_c1, cnt_c1);
    k_scatter256<<<nb((long long)Ew1 * 64, 256), 256>>>(ha, ew1, ew1 + Ew1, Ew1, (int)NP_H01, agg_w1, cnt_w1);

    // 5) normalize (K=256 -> 64 float4/row -> shift 6)
    k_norm<<<nb(NP_H01 * 64, 256), 256>>>(agg_c1, cnt_c1, NP_H01 * 64, 6);
    k_norm<<<nb(NP_H01 * 64, 256), 256>>>(agg_w1, cnt_w1, NP_H01 * 64, 6);

    // 6) layer-1 GEMM (+bias, relu) -> xp1
    {
        dim3 g((unsigned)((NP_H01 + 127) / 128), 2);
        k_gemm_ms<<<g, 256>>>(agg_c1, l1c_Wl, 256,
                              agg_w1, l1w_Wl, 256,
                              hp, Wr1, 256,
                              b1, xp1, (int)NP_H01, 256, 1);
    }

    // 7) final linear: out = xp1 @ lin_W + lin_b   (N=64, single N-tile)
    {
        dim3 g((unsigned)((NP_H01 + 127) / 128), 1);
        k_gemm_ms<<<g, 256>>>(xp1, lin_W, 256,
                              nullptr, nullptr, 0,
                              nullptr, nullptr, 0,
                              lin_b, (float*)d_out, (int)NP_H01, 64, 0);
    }
}